// round 12
// baseline (speedup 1.0000x reference)
#include <cuda_runtime.h>

// SRNN_Softmax: one stack-RNN step, SINGLE persistent kernel, grid-strided
// 4-row chunks at high occupancy (6 blocks/SM), sense-reversing grid barrier
// between phases. W_y kept L2-resident across graph replays (evict-normal +
// prefetch); single-use W_ih/W_hh streams are evict-first (__ldcs).
// Output layout (fp32): [0:O) output | [O:O+H) hidden | [O+H:O+H+M) stack | [O+H+M] weights

constexpr int H = 4096;
constexpr int V = 4096;
constexpr int O = 4096;
constexpr int M = 104;

constexpr int THREADS = 256;
constexpr int NW      = THREADS / 32;
constexpr int CR      = 4;                 // rows per chunk
constexpr int NCHUNK  = H / CR;            // 1024 chunks per phase
constexpr int GRID    = 888;               // 6 blocks/SM x 148 SMs, all resident

__device__ float g_h[H];
__device__ unsigned g_cnt = 0;
__device__ volatile unsigned g_sense = 0;

__device__ __forceinline__ float warp_sum(float v) {
#pragma unroll
    for (int o = 16; o > 0; o >>= 1) v += __shfl_down_sync(0xffffffffu, v, o);
    return v;
}

__device__ __forceinline__ void l2_prefetch(const void* p) {
    asm volatile("prefetch.global.L2 [%0];" :: "l"(p));
}

// Sense-reversing grid barrier (one use per launch; replay-safe).
__device__ __forceinline__ void grid_barrier() {
    __syncthreads();
    if (threadIdx.x == 0) {
        __threadfence();                       // publish g_h stores
        const unsigned s = g_sense;
        if (atomicAdd(&g_cnt, 1u) == GRID - 1u) {
            g_cnt = 0u;
            __threadfence();
            g_sense = s ^ 1u;
        } else {
            while (g_sense == s) { __nanosleep(128); }
        }
    }
    __syncthreads();
}

__global__ void __launch_bounds__(THREADS, 6)
fused_kernel(const float* __restrict__ E, const int* __restrict__ inp,
             const float* __restrict__ W_ih, const float* __restrict__ b_ih,
             const float* __restrict__ W_hh, const float* __restrict__ b_hh,
             const float* __restrict__ W_sh, const float* __restrict__ b_sh,
             const float* __restrict__ hidden0, const float* __restrict__ stack,
             const float* __restrict__ W_y, const float* __restrict__ b_y,
             const float* __restrict__ W_a, const float* __restrict__ b_a,
             const float* __restrict__ W_n, const float* __restrict__ b_n,
             float* __restrict__ out) {
    __shared__ float sred[CR][NW];
    __shared__ float ssmall[3];

    const int lane = threadIdx.x & 31;
    const int w    = threadIdx.x >> 5;

    // ---------------- Phase 1: h GEMV, grid-strided 4-row chunks ----------
    // Per chunk: interleaved 4xW_ih + 4xW_hh streams (R5-measured 40-reg shape).
    {
        const float   s0   = stack[0];
        const float4* emb4 = (const float4*)(E + (size_t)inp[0] * V);
        const float4* ws4  = (const float4*)W_sh;
        const float4* bs4  = (const float4*)b_sh;
        const float4* h04  = (const float4*)hidden0;

        for (int c = blockIdx.x; c < NCHUNK; c += GRID) {
            const int row0 = c * CR;
            float acc[CR];
#pragma unroll
            for (int r = 0; r < CR; ++r) acc[r] = 0.f;

            const float4* wi[CR];
            const float4* wh[CR];
#pragma unroll
            for (int r = 0; r < CR; ++r) {
                wi[r] = (const float4*)(W_ih + (size_t)(row0 + r) * V);
                wh[r] = (const float4*)(W_hh + (size_t)(row0 + r) * H);
            }

#pragma unroll
            for (int it = 0; it < (V / 4) / THREADS; ++it) {
                const int j = it * THREADS + threadIdx.x;
                const float4 e  = __ldg(emb4 + j);
                const float4 ws = __ldg(ws4 + j);
                const float4 bs = __ldg(bs4 + j);
                const float4 h0 = __ldg(h04 + j);
                float4 hb;
                hb.x = fmaf(ws.x, s0, bs.x + h0.x);
                hb.y = fmaf(ws.y, s0, bs.y + h0.y);
                hb.z = fmaf(ws.z, s0, bs.z + h0.z);
                hb.w = fmaf(ws.w, s0, bs.w + h0.w);
#pragma unroll
                for (int r = 0; r < CR; ++r) {
                    const float4 a = __ldcs(wi[r] + j);
                    const float4 b = __ldcs(wh[r] + j);
                    acc[r] = fmaf(a.x, e.x,  acc[r]);
                    acc[r] = fmaf(a.y, e.y,  acc[r]);
                    acc[r] = fmaf(a.z, e.z,  acc[r]);
                    acc[r] = fmaf(a.w, e.w,  acc[r]);
                    acc[r] = fmaf(b.x, hb.x, acc[r]);
                    acc[r] = fmaf(b.y, hb.y, acc[r]);
                    acc[r] = fmaf(b.z, hb.z, acc[r]);
                    acc[r] = fmaf(b.w, hb.w, acc[r]);
                }
            }

#pragma unroll
            for (int r = 0; r < CR; ++r) {
                const float v = warp_sum(acc[r]);
                if (lane == 0) sred[r][w] = v;
            }
            __syncthreads();
            if (threadIdx.x < CR) {
                const int r = threadIdx.x;
                float t = 0.f;
#pragma unroll
                for (int k = 0; k < NW; ++k) t += sred[r][k];
                const int row = row0 + r;
                const float hv = tanhf(t + b_ih[row] + b_hh[row]);
                g_h[row]     = hv;
                out[O + row] = hv;
            }
            __syncthreads();   // sred safe for next chunk
        }
    }

    // Prefetch W_y rows of this block's phase-2 chunks into L2 (warmup streams
    // them during the straggler window; steady state: near-free recency renew).
    for (int c = blockIdx.x; c < NCHUNK; c += GRID) {
        const char* wy_base = (const char*)(W_y + (size_t)(c * CR) * H);
        for (int b = threadIdx.x; b < (CR * H * 4) / 128; b += THREADS)
            l2_prefetch(wy_base + b * 128);
    }

    grid_barrier();

    // ---------------- Phase 2: y GEMV + small dots, grid-strided -----------
    const float4* h4 = (const float4*)g_h;
    for (int c = blockIdx.x; c < NCHUNK + 1; c += GRID) {
        if (c < NCHUNK) {
            const int row0 = c * CR;
            float acc[CR];
#pragma unroll
            for (int r = 0; r < CR; ++r) acc[r] = 0.f;

            const float4* wy[CR];
#pragma unroll
            for (int r = 0; r < CR; ++r)
                wy[r] = (const float4*)(W_y + (size_t)(row0 + r) * H);

#pragma unroll
            for (int it = 0; it < (H / 4) / THREADS; ++it) {
                const int j = it * THREADS + threadIdx.x;
                const float4 hh = __ldcg(h4 + j);
#pragma unroll
                for (int r = 0; r < CR; ++r) {
                    const float4 a = __ldg(wy[r] + j);   // evict-normal: stays in L2
                    acc[r] = fmaf(a.x, hh.x, acc[r]);
                    acc[r] = fmaf(a.y, hh.y, acc[r]);
                    acc[r] = fmaf(a.z, hh.z, acc[r]);
                    acc[r] = fmaf(a.w, hh.w, acc[r]);
                }
            }

#pragma unroll
            for (int r = 0; r < CR; ++r) {
                const float v = warp_sum(acc[r]);
                if (lane == 0) sred[r][w] = v;
            }
            __syncthreads();
            if (threadIdx.x < CR) {
                const int r = threadIdx.x;
                float t = 0.f;
#pragma unroll
                for (int k = 0; k < NW; ++k) t += sred[r][k];
                const int row = row0 + r;
                out[row] = 1.f / (1.f + expf(-(t + b_y[row])));
            }
            __syncthreads();
        } else {
            // chunk NCHUNK: small dots + finalize
            const float4* wa0 = (const float4*)W_a;
            const float4* wa1 = (const float4*)(W_a + H);
            const float4* wn  = (const float4*)W_n;
            float a0 = 0.f, a1 = 0.f, an = 0.f;
#pragma unroll
            for (int it = 0; it < (H / 4) / THREADS; ++it) {
                const int j = it * THREADS + threadIdx.x;
                const float4 hh = __ldcg(h4 + j);
                const float4 x0 = __ldg(wa0 + j);
                const float4 x1 = __ldg(wa1 + j);
                const float4 x2 = __ldg(wn + j);
                a0 = fmaf(x0.x, hh.x, a0); a0 = fmaf(x0.y, hh.y, a0);
                a0 = fmaf(x0.z, hh.z, a0); a0 = fmaf(x0.w, hh.w, a0);
                a1 = fmaf(x1.x, hh.x, a1); a1 = fmaf(x1.y, hh.y, a1);
                a1 = fmaf(x1.z, hh.z, a1); a1 = fmaf(x1.w, hh.w, a1);
                an = fmaf(x2.x, hh.x, an); an = fmaf(x2.y, hh.y, an);
                an = fmaf(x2.z, hh.z, an); an = fmaf(x2.w, hh.w, an);
            }
            const float v0 = warp_sum(a0);
            const float v1 = warp_sum(a1);
            const float v2 = warp_sum(an);
            if (lane == 0) { sred[0][w] = v0; sred[1][w] = v1; sred[2][w] = v2; }
            __syncthreads();
            if (threadIdx.x < 3) {
                const int r = threadIdx.x;
                float t = 0.f;
#pragma unroll
                for (int k = 0; k < NW; ++k) t += sred[r][k];
                ssmall[r] = t;
            }
            __syncthreads();

            const float l0 = ssmall[0] + b_a[0];
            const float l1 = ssmall[1] + b_a[1];
            const float mx = fmaxf(l0, l1);
            const float e0 = expf(l0 - mx);
            const float e1 = expf(l1 - mx);
            const float inv = 1.f / (e0 + e1);
            const float aw0 = e0 * inv;
            const float aw1 = e1 * inv;
            const float ne  = 1.f / (1.f + expf(-(ssmall[2] + b_n[0])));

            const int i = threadIdx.x;
            if (i < M) {
                const float push = (i == 0) ? ne : stack[i - 1];
                const float pop  = (i < M - 1) ? stack[i + 1] : 0.f;
                out[O + H + i] = aw0 * push + aw1 * pop;
            }
            if (i == 0) out[O + H + M] = aw0 + aw1;
            __syncthreads();
        }
    }
}

// ---------------------------------------------------------------------------
extern "C" void kernel_launch(void* const* d_in, const int* in_sizes, int n_in,
                              void* d_out, int out_size) {
    const int*   inp     = (const int*)  d_in[0];
    const float* hidden0 = (const float*)d_in[1];
    const float* stack   = (const float*)d_in[2];
    const float* E       = (const float*)d_in[3];
    const float* W_ih    = (const float*)d_in[4];
    const float* b_ih    = (const float*)d_in[5];
    const float* W_hh    = (const float*)d_in[6];
    const float* b_hh    = (const float*)d_in[7];
    const float* W_y     = (const float*)d_in[8];
    const float* b_y     = (const float*)d_in[9];
    const float* W_n     = (const float*)d_in[10];
    const float* b_n     = (const float*)d_in[11];
    const float* W_a     = (const float*)d_in[12];
    const float* b_a     = (const float*)d_in[13];
    const float* W_sh    = (const float*)d_in[14];
    const float* b_sh    = (const float*)d_in[15];
    float* out = (float*)d_out;

    fused_kernel<<<GRID, THREADS>>>(E, inp, W_ih, b_ih, W_hh, b_hh,
                                    W_sh, b_sh, hidden0, stack,
                                    W_y, b_y, W_a, b_a, W_n, b_n, out);
}

// round 14
// speedup vs baseline: 1.4670x; 1.4670x over previous
#include <cuda_runtime.h>

// SRNN_Softmax: one stack-RNN step, two kernels, measured-best shapes.
//  k1 (h): 1024 blocks x 4 interleaved rows (W_ih+W_hh, __ldcs) — the R5 shape
//          measured at 5.4 TB/s; afterwards each block L2-prefetches its 4 W_y
//          rows (steady state: renews residency; warmup: streams them early).
//  k2 (y): 1024 blocks x 4 rows, W_y read evict-normal (stays L2-resident
//          across graph replays); +1 tail block for small dots + finalize.
// Output layout (fp32): [0:O) output | [O:O+H) hidden | [O+H:O+H+M) stack | [O+H+M] weights

constexpr int H = 4096;
constexpr int V = 4096;
constexpr int O = 4096;
constexpr int M = 104;

constexpr int CR      = 4;
constexpr int THREADS = 256;
constexpr int NW      = THREADS / 32;

__device__ float g_h[H];

__device__ __forceinline__ float warp_sum(float v) {
#pragma unroll
    for (int o = 16; o > 0; o >>= 1) v += __shfl_down_sync(0xffffffffu, v, o);
    return v;
}

__device__ __forceinline__ void l2_prefetch(const void* p) {
    asm volatile("prefetch.global.L2 [%0];" :: "l"(p));
}

// ---------------------------------------------------------------------------
// Kernel 1: h = tanh(W_ih@emb + W_hh@hbar + b_ih + b_hh), hbar inlined.
// 1024 blocks, 4 rows each, 8 interleaved __ldcs streams (R5-measured shape).
// ---------------------------------------------------------------------------
__global__ void __launch_bounds__(THREADS)
h_kernel(const float* __restrict__ E, const int* __restrict__ inp,
         const float* __restrict__ W_ih, const float* __restrict__ b_ih,
         const float* __restrict__ W_hh, const float* __restrict__ b_hh,
         const float* __restrict__ W_sh, const float* __restrict__ b_sh,
         const float* __restrict__ hidden0, const float* __restrict__ stack,
         const float* __restrict__ W_y,
         float* __restrict__ out) {
    __shared__ float sred[CR][NW];

    const float   s0   = stack[0];
    const float4* emb4 = (const float4*)(E + (size_t)inp[0] * V);
    const float4* ws4  = (const float4*)W_sh;
    const float4* bs4  = (const float4*)b_sh;
    const float4* h04  = (const float4*)hidden0;

    const int row0 = blockIdx.x * CR;
    float acc[CR];
#pragma unroll
    for (int r = 0; r < CR; ++r) acc[r] = 0.f;

    const float4* wi[CR];
    const float4* wh[CR];
#pragma unroll
    for (int r = 0; r < CR; ++r) {
        wi[r] = (const float4*)(W_ih + (size_t)(row0 + r) * V);
        wh[r] = (const float4*)(W_hh + (size_t)(row0 + r) * H);
    }

#pragma unroll
    for (int it = 0; it < (V / 4) / THREADS; ++it) {
        const int j = it * THREADS + threadIdx.x;
        const float4 e  = __ldg(emb4 + j);
        const float4 ws = __ldg(ws4 + j);
        const float4 bs = __ldg(bs4 + j);
        const float4 h0 = __ldg(h04 + j);
        float4 hb;
        hb.x = fmaf(ws.x, s0, bs.x + h0.x);
        hb.y = fmaf(ws.y, s0, bs.y + h0.y);
        hb.z = fmaf(ws.z, s0, bs.z + h0.z);
        hb.w = fmaf(ws.w, s0, bs.w + h0.w);
#pragma unroll
        for (int r = 0; r < CR; ++r) {
            const float4 a = __ldcs(wi[r] + j);
            const float4 b = __ldcs(wh[r] + j);
            acc[r] = fmaf(a.x, e.x,  acc[r]);
            acc[r] = fmaf(a.y, e.y,  acc[r]);
            acc[r] = fmaf(a.z, e.z,  acc[r]);
            acc[r] = fmaf(a.w, e.w,  acc[r]);
            acc[r] = fmaf(b.x, hb.x, acc[r]);
            acc[r] = fmaf(b.y, hb.y, acc[r]);
            acc[r] = fmaf(b.z, hb.z, acc[r]);
            acc[r] = fmaf(b.w, hb.w, acc[r]);
        }
    }

    const int lane = threadIdx.x & 31;
    const int w    = threadIdx.x >> 5;
#pragma unroll
    for (int r = 0; r < CR; ++r) {
        const float v = warp_sum(acc[r]);
        if (lane == 0) sred[r][w] = v;
    }
    __syncthreads();

    if (threadIdx.x < CR) {
        const int r = threadIdx.x;
        float t = 0.f;
#pragma unroll
        for (int k = 0; k < NW; ++k) t += sred[r][k];
        const int row = row0 + r;
        const float hv = tanhf(t + b_ih[row] + b_hh[row]);
        g_h[row]     = hv;
        out[O + row] = hv;
    }

    // Renew/warm this block's 4 W_y rows in L2 (64 KB) while other h-blocks
    // still stream; in steady state the lines are resident and this is cheap.
    {
        const char* wy_base = (const char*)(W_y + (size_t)row0 * H);
        for (int c = threadIdx.x; c < (CR * H * 4) / 128; c += THREADS)
            l2_prefetch(wy_base + c * 128);
    }
}

// ---------------------------------------------------------------------------
// Kernel 2: out = sigmoid(W_y@h + b_y), 1024 blocks x 4 rows (W_y evict-normal
// -> L2-resident across replays); tail block: small dots + finalize.
// ---------------------------------------------------------------------------
__global__ void __launch_bounds__(THREADS)
y_kernel(const float* __restrict__ W_y, const float* __restrict__ b_y,
         const float* __restrict__ W_a, const float* __restrict__ b_a,
         const float* __restrict__ W_n, const float* __restrict__ b_n,
         const float* __restrict__ stack,
         float* __restrict__ out) {
    __shared__ float sred[CR][NW];
    __shared__ float ssmall[3];
    const int lane = threadIdx.x & 31;
    const int w    = threadIdx.x >> 5;
    const float4* h4 = (const float4*)g_h;

    if (blockIdx.x < H / CR) {
        const int row0 = blockIdx.x * CR;
        float acc[CR];
#pragma unroll
        for (int r = 0; r < CR; ++r) acc[r] = 0.f;

        const float4* wy[CR];
#pragma unroll
        for (int r = 0; r < CR; ++r)
            wy[r] = (const float4*)(W_y + (size_t)(row0 + r) * H);

#pragma unroll
        for (int it = 0; it < (H / 4) / THREADS; ++it) {
            const int j = it * THREADS + threadIdx.x;
            const float4 hh = __ldg(h4 + j);
#pragma unroll
            for (int r = 0; r < CR; ++r) {
                const float4 a = __ldg(wy[r] + j);   // evict-normal: stays in L2
                acc[r] = fmaf(a.x, hh.x, acc[r]);
                acc[r] = fmaf(a.y, hh.y, acc[r]);
                acc[r] = fmaf(a.z, hh.z, acc[r]);
                acc[r] = fmaf(a.w, hh.w, acc[r]);
            }
        }

#pragma unroll
        for (int r = 0; r < CR; ++r) {
            const float v = warp_sum(acc[r]);
            if (lane == 0) sred[r][w] = v;
        }
        __syncthreads();

        if (threadIdx.x < CR) {
            const int r = threadIdx.x;
            float t = 0.f;
#pragma unroll
            for (int k = 0; k < NW; ++k) t += sred[r][k];
            const int row = row0 + r;
            out[row] = 1.f / (1.f + expf(-(t + b_y[row])));
        }
    } else {
        // Tail block: W_a (2 rows) + W_n (1 row) dots, then finalize.
        const float4* wa0 = (const float4*)W_a;
        const float4* wa1 = (const float4*)(W_a + H);
        const float4* wn  = (const float4*)W_n;
        float a0 = 0.f, a1 = 0.f, an = 0.f;
#pragma unroll
        for (int it = 0; it < (H / 4) / THREADS; ++it) {
            const int j = it * THREADS + threadIdx.x;
            const float4 hh = __ldg(h4 + j);
            const float4 x0 = __ldg(wa0 + j);
            const float4 x1 = __ldg(wa1 + j);
            const float4 x2 = __ldg(wn + j);
            a0 = fmaf(x0.x, hh.x, a0); a0 = fmaf(x0.y, hh.y, a0);
            a0 = fmaf(x0.z, hh.z, a0); a0 = fmaf(x0.w, hh.w, a0);
            a1 = fmaf(x1.x, hh.x, a1); a1 = fmaf(x1.y, hh.y, a1);
            a1 = fmaf(x1.z, hh.z, a1); a1 = fmaf(x1.w, hh.w, a1);
            an = fmaf(x2.x, hh.x, an); an = fmaf(x2.y, hh.y, an);
            an = fmaf(x2.z, hh.z, an); an = fmaf(x2.w, hh.w, an);
        }
        const float v0 = warp_sum(a0);
        const float v1 = warp_sum(a1);
        const float v2 = warp_sum(an);
        if (lane == 0) { sred[0][w] = v0; sred[1][w] = v1; sred[2][w] = v2; }
        __syncthreads();
        if (threadIdx.x < 3) {
            const int r = threadIdx.x;
            float t = 0.f;
#pragma unroll
            for (int k = 0; k < NW; ++k) t += sred[r][k];
            ssmall[r] = t;
        }
        __syncthreads();

        const float l0 = ssmall[0] + b_a[0];
        const float l1 = ssmall[1] + b_a[1];
        const float mx = fmaxf(l0, l1);
        const float e0 = expf(l0 - mx);
        const float e1 = expf(l1 - mx);
        const float inv = 1.f / (e0 + e1);
        const float aw0 = e0 * inv;
        const float aw1 = e1 * inv;
        const float ne  = 1.f / (1.f + expf(-(ssmall[2] + b_n[0])));

        const int i = threadIdx.x;
        if (i < M) {
            const float push = (i == 0) ? ne : stack[i - 1];
            const float pop  = (i < M - 1) ? stack[i + 1] : 0.f;
            out[O + H + i] = aw0 * push + aw1 * pop;
        }
        if (i == 0) out[O + H + M] = aw0 + aw1;
    }
}

// ---------------------------------------------------------------------------
extern "C" void kernel_launch(void* const* d_in, const int* in_sizes, int n_in,
                              void* d_out, int out_size) {
    const int*   inp     = (const int*)  d_in[0];
    const float* hidden0 = (const float*)d_in[1];
    const float* stack   = (const float*)d_in[2];
    const float* E       = (const float*)d_in[3];
    const float* W_ih    = (const float*)d_in[4];
    const float* b_ih    = (const float*)d_in[5];
    const float* W_hh    = (const float*)d_in[6];
    const float* b_hh    = (const float*)d_in[7];
    const float* W_y     = (const float*)d_in[8];
    const float* b_y     = (const float*)d_in[9];
    const float* W_n     = (const float*)d_in[10];
    const float* b_n     = (const float*)d_in[11];
    const float* W_a     = (const float*)d_in[12];
    const float* b_a     = (const float*)d_in[13];
    const float* W_sh    = (const float*)d_in[14];
    const float* b_sh    = (const float*)d_in[15];
    float* out = (float*)d_out;

    h_kernel<<<H / CR, THREADS>>>(E, inp, W_ih, b_ih, W_hh, b_hh,
                                  W_sh, b_sh, hidden0, stack, W_y, out);
    y_kernel<<<H / CR + 1, THREADS>>>(W_y, b_y, W_a, b_a, W_n, b_n, stack, out);
}